// round 2
// baseline (speedup 1.0000x reference)
#include <cuda_runtime.h>
#include <cstdint>

#define HID 256
#define AH  32
#define NU  10000
#define NI  30000
#define NN  40000
#define NE  500000
#define THRESH 0.8f

// ---------------- device scratch (no allocations allowed) ----------------
__device__ float g_UW1[NU * AH];        // user @ W1_top + b1
__device__ float g_IW1[NI * AH];        // item @ W1_bot
__device__ float g_w[NE];               // raw sigmoid edge weights
__device__ float g_xw[(size_t)NN * HID];// x @ gcn_W
__device__ float g_deg[NN];
__device__ float g_dinv[NN];
__device__ int   g_cnt[NN];
__device__ int   g_off[NN];
__device__ int   g_cur[NN];
__device__ int   g_srcl[NE];            // CSR: src per kept edge
__device__ float g_coef[NE];            // CSR: dinv[src]*dinv[dst]
__device__ unsigned long long g_amax;   // packed argmax (w_bits<<32)|(~e)
__device__ int   g_kept;

// ---------------- K0: reset per-replay state ----------------
__global__ void k_init() {
    int i = blockIdx.x * blockDim.x + threadIdx.x;
    if (i < NN) { g_deg[i] = 1.0f; g_cnt[i] = 0; }
    if (i == 0) { g_amax = 0ULL; g_kept = 0; }
}

// ---------------- K1: node projections through attn_W1 ----------------
// warp per node row; lane = output channel (AH=32)
__global__ void k_proj(const float* __restrict__ U, const float* __restrict__ I,
                       const float* __restrict__ W1, const float* __restrict__ b1) {
    int g = blockIdx.x * blockDim.x + threadIdx.x;
    int row = g >> 5, lane = g & 31;
    if (row >= NN) return;
    const float* x; const float* W; float* out; float acc;
    if (row < NU) {
        x = U + (size_t)row * HID; W = W1;            out = g_UW1 + row * AH;
        acc = b1[lane];
    } else {
        int r = row - NU;
        x = I + (size_t)r * HID;   W = W1 + HID * AH; out = g_IW1 + r * AH;
        acc = 0.0f;
    }
    #pragma unroll 8
    for (int k = 0; k < HID; k++)
        acc += x[k] * W[k * AH + lane];
    out[lane] = acc;
}

// ---------------- K2: per-edge attention weight + global stats ----------------
__global__ void k_edge(const int* __restrict__ ei, const float* __restrict__ W2,
                       const float* __restrict__ b2, int E) {
    __shared__ float sW2[AH];
    if (threadIdx.x < AH) sW2[threadIdx.x] = W2[threadIdx.x];
    __syncthreads();
    int e = blockIdx.x * blockDim.x + threadIdx.x;
    float w = -1.0f;
    if (e < E) {
        int s = ei[e], d = ei[E + e];
        const float4* u4 = (const float4*)(g_UW1 + (size_t)s * AH);
        const float4* v4 = (const float4*)(g_IW1 + (size_t)d * AH);
        float z = b2[0];
        #pragma unroll
        for (int j = 0; j < AH / 4; j++) {
            float4 a = u4[j], b = v4[j];
            float h0 = a.x + b.x, h1 = a.y + b.y, h2 = a.z + b.z, h3 = a.w + b.w;
            h0 = h0 >= 0.f ? h0 : 0.2f * h0;
            h1 = h1 >= 0.f ? h1 : 0.2f * h1;
            h2 = h2 >= 0.f ? h2 : 0.2f * h2;
            h3 = h3 >= 0.f ? h3 : 0.2f * h3;
            z += h0 * sW2[4*j] + h1 * sW2[4*j+1] + h2 * sW2[4*j+2] + h3 * sW2[4*j+3];
        }
        w = 1.0f / (1.0f + expf(-z));
        g_w[e] = w;
    }
    unsigned kb = __ballot_sync(0xFFFFFFFFu, w > THRESH);
    unsigned long long p = 0ULL;
    if (e < E)
        p = (((unsigned long long)__float_as_uint(w)) << 32)
          | (unsigned long long)(0xFFFFFFFFu - (unsigned)e);
    #pragma unroll
    for (int o = 16; o > 0; o >>= 1) {
        unsigned long long q = __shfl_down_sync(0xFFFFFFFFu, p, o);
        if (q > p) p = q;
    }
    if ((threadIdx.x & 31) == 0) {
        if (kb) atomicAdd(&g_kept, __popc(kb));
        atomicMax(&g_amax, p);
    }
}

__device__ __forceinline__ bool edge_kept(int e, float w) {
    if (g_kept > 0) return (w > THRESH);
    int am = (int)(0xFFFFFFFFu - (unsigned)(g_amax & 0xFFFFFFFFull));
    return (e == am);
}

// ---------------- K3: mask, denoised weights out, degree + histogram ----------------
__global__ void k_mask(const int* __restrict__ ei, float* __restrict__ wout, int E) {
    int e = blockIdx.x * blockDim.x + threadIdx.x;
    if (e >= E) return;
    float w = g_w[e];
    bool keep = edge_kept(e, w);
    wout[e] = keep ? w : 0.0f;
    if (keep) {
        int d = ei[E + e];
        atomicAdd(&g_deg[d], 1.0f);
        atomicAdd(&g_cnt[d], 1);
    }
}

// ---------------- K4a: dinv ----------------
__global__ void k_dinv() {
    int i = blockIdx.x * blockDim.x + threadIdx.x;
    if (i < NN) g_dinv[i] = rsqrtf(g_deg[i]);
}

// ---------------- K4b: single-block exclusive scan of g_cnt ----------------
__global__ void k_scan() {
    __shared__ int sh[1024];
    __shared__ int scarry;
    if (threadIdx.x == 0) scarry = 0;
    __syncthreads();
    for (int base = 0; base < NN; base += 1024) {
        int i = base + threadIdx.x;
        int v = (i < NN) ? g_cnt[i] : 0;
        sh[threadIdx.x] = v;
        __syncthreads();
        for (int o = 1; o < 1024; o <<= 1) {
            int t = (threadIdx.x >= o) ? sh[threadIdx.x - o] : 0;
            __syncthreads();
            sh[threadIdx.x] += t;
            __syncthreads();
        }
        int c = scarry;
        int excl = c + sh[threadIdx.x] - v;
        if (i < NN) { g_off[i] = excl; g_cur[i] = excl; }
        __syncthreads();
        if (threadIdx.x == 1023) scarry = c + sh[1023];
        __syncthreads();
    }
}

// ---------------- K5: CSR bucket fill (kept edges only) ----------------
__global__ void k_fill(const int* __restrict__ ei, int E) {
    int e = blockIdx.x * blockDim.x + threadIdx.x;
    if (e >= E) return;
    float w = g_w[e];
    if (!edge_kept(e, w)) return;
    int s = ei[e], d = ei[E + e];
    int p = atomicAdd(&g_cur[d], 1);
    g_srcl[p] = s;
    g_coef[p] = g_dinv[s] * g_dinv[d];
}

// ---------------- K6: xw = concat(U,I) @ gcn_W  (fp32 tiled GEMM) ----------------
__global__ void k_gemm(const float* __restrict__ U, const float* __restrict__ I,
                       const float* __restrict__ W) {
    __shared__ float As[16][64];
    __shared__ float Bs[16][64];
    int m0 = blockIdx.x * 64, n0 = blockIdx.y * 64;
    int tid = threadIdx.x;
    int tr = tid >> 4, tc = tid & 15;
    float acc[4][4] = {};
    for (int kk = 0; kk < HID; kk += 16) {
        #pragma unroll
        for (int rep = 0; rep < 4; rep++) {
            int id = rep * 256 + tid;
            int r = id >> 4, c = id & 15;
            int m = m0 + r;
            const float* xr = (m < NU) ? U + (size_t)m * HID
                                       : I + (size_t)(m - NU) * HID;
            As[c][r] = xr[kk + c];
        }
        #pragma unroll
        for (int rep = 0; rep < 4; rep++) {
            int id = rep * 256 + tid;
            int r = id >> 6, c = id & 63;
            Bs[r][c] = W[(kk + r) * HID + n0 + c];
        }
        __syncthreads();
        #pragma unroll
        for (int k = 0; k < 16; k++) {
            float4 a = *(const float4*)&As[k][tr * 4];
            float4 b = *(const float4*)&Bs[k][tc * 4];
            acc[0][0] += a.x * b.x; acc[0][1] += a.x * b.y; acc[0][2] += a.x * b.z; acc[0][3] += a.x * b.w;
            acc[1][0] += a.y * b.x; acc[1][1] += a.y * b.y; acc[1][2] += a.y * b.z; acc[1][3] += a.y * b.w;
            acc[2][0] += a.z * b.x; acc[2][1] += a.z * b.y; acc[2][2] += a.z * b.z; acc[2][3] += a.z * b.w;
            acc[3][0] += a.w * b.x; acc[3][1] += a.w * b.y; acc[3][2] += a.w * b.z; acc[3][3] += a.w * b.w;
        }
        __syncthreads();
    }
    #pragma unroll
    for (int i = 0; i < 4; i++) {
        int m = m0 + tr * 4 + i;
        float4 v = make_float4(acc[i][0], acc[i][1], acc[i][2], acc[i][3]);
        *(float4*)&g_xw[(size_t)m * HID + n0 + tc * 4] = v;
    }
}

// ---------------- K7: per-node aggregate + self-loop + bias ----------------
__global__ void k_agg(const float* __restrict__ bias, float* __restrict__ out) {
    int n = blockIdx.x, t = threadIdx.x;
    __shared__ int   ss[64];
    __shared__ float sc[64];
    float di = g_dinv[n];
    float acc = g_xw[(size_t)n * HID + t] * (di * di) + bias[t];
    int beg = g_off[n], cnt = g_cnt[n];
    for (int base = 0; base < cnt; base += 64) {
        int nb = min(64, cnt - base);
        if (t < nb) {
            ss[t] = g_srcl[beg + base + t];
            sc[t] = g_coef[beg + base + t];
        }
        __syncthreads();
        for (int j = 0; j < nb; j++)
            acc += sc[j] * g_xw[(size_t)ss[j] * HID + t];
        __syncthreads();
    }
    out[(size_t)n * HID + t] = acc;
}

// ---------------- launch ----------------
extern "C" void kernel_launch(void* const* d_in, const int* in_sizes, int n_in,
                              void* d_out, int out_size) {
    const float* U  = (const float*)d_in[0];
    const float* I  = (const float*)d_in[1];
    const int*   ei = (const int*)  d_in[2];
    const float* W1 = (const float*)d_in[3];
    const float* b1 = (const float*)d_in[4];
    const float* W2 = (const float*)d_in[5];
    const float* b2 = (const float*)d_in[6];
    const float* GW = (const float*)d_in[7];
    const float* Gb = (const float*)d_in[8];
    int E = in_sizes[2] / 2;

    float* out  = (float*)d_out;                 // [NN, HID]
    float* wout = out + (size_t)NN * HID;        // [E]

    k_init<<<(NN + 255) / 256, 256>>>();
    k_proj<<<(NN * 32 + 255) / 256, 256>>>(U, I, W1, b1);
    k_gemm<<<dim3(NN / 64, HID / 64), 256>>>(U, I, GW);   // independent; overlap-friendly
    k_edge<<<(E + 255) / 256, 256>>>(ei, W2, b2, E);
    k_mask<<<(E + 255) / 256, 256>>>(ei, wout, E);
    k_dinv<<<(NN + 255) / 256, 256>>>();
    k_scan<<<1, 1024>>>();
    k_fill<<<(E + 255) / 256, 256>>>(ei, E);
    k_agg<<<NN, 256>>>(Gb, out);
}

// round 4
// speedup vs baseline: 1.3081x; 1.3081x over previous
#include <cuda_runtime.h>
#include <cstdint>

#define HID 256
#define AH  32
#define NU  10000
#define NI  30000
#define NN  40000
#define NE  500000
#define THRESH 0.8f

typedef unsigned long long ull;

// ---------------- device scratch ----------------
__device__ float g_UW1[NU * AH];
__device__ float g_IW1[NI * AH];
__device__ float g_w[NE];
__device__ float g_xw[(size_t)NN * HID];
__device__ float g_dinv[NN];
__device__ int   g_cnt[NN];
__device__ int   g_off[NN];
__device__ int   g_cur[NN];
__device__ int   g_srcl[NE];
__device__ float g_coef[NE];
__device__ ull   g_amax;
__device__ int   g_kept;

// ---------------- f32x2 packed helpers ----------------
__device__ __forceinline__ ull pk2(float x, float y) {
    ull r;
    asm("mov.b64 %0, {%1, %2};" : "=l"(r) : "f"(x), "f"(y));
    return r;
}
__device__ __forceinline__ void ffma2(ull& d, ull a, ull b) {
    asm("fma.rn.f32x2 %0, %1, %2, %0;" : "+l"(d) : "l"(a), "l"(b));
}

// ---------------- K0: reset ----------------
__global__ void k_init() {
    int i = blockIdx.x * blockDim.x + threadIdx.x;
    if (i < NN) g_cnt[i] = 0;
    if (i == 0) { g_amax = 0ULL; g_kept = 0; }
}

// ---------------- K1: node projections through attn_W1 ----------------
__global__ void k_proj(const float* __restrict__ U, const float* __restrict__ I,
                       const float* __restrict__ W1, const float* __restrict__ b1) {
    int g = blockIdx.x * blockDim.x + threadIdx.x;
    int row = g >> 5, lane = g & 31;
    if (row >= NN) return;
    const float* x; const float* W; float* out; float acc0;
    if (row < NU) {
        x = U + (size_t)row * HID; W = W1;            out = g_UW1 + row * AH;
        acc0 = b1[lane];
    } else {
        int r = row - NU;
        x = I + (size_t)r * HID;   W = W1 + HID * AH; out = g_IW1 + r * AH;
        acc0 = 0.0f;
    }
    float acc1 = 0.0f;
    #pragma unroll 4
    for (int k = 0; k < HID; k += 2) {
        acc0 += x[k]     * W[k * AH + lane];
        acc1 += x[k + 1] * W[(k + 1) * AH + lane];
    }
    out[lane] = acc0 + acc1;
}

// ---------------- K2: edge attention (8 lanes per edge) ----------------
__global__ void k_edge(const int* __restrict__ ei, const float* __restrict__ W2,
                       const float* __restrict__ b2, int E) {
    __shared__ float sW2[AH];
    __shared__ ull   blkmax;
    __shared__ int   blkkept;
    int tid = threadIdx.x;
    if (tid < AH) sW2[tid] = W2[tid];
    if (tid == 0) { blkmax = 0ULL; blkkept = 0; }
    __syncthreads();

    int lane = tid & 31;
    int gw = (blockIdx.x * blockDim.x + tid) >> 5;
    int sub = lane >> 3, part = lane & 7;
    int e = gw * 4 + sub;
    bool valid = e < E;
    int s = 0, d = 0;
    if (valid) { s = ei[e]; d = ei[E + e]; }

    float4 a = *(const float4*)(g_UW1 + (size_t)s * AH + part * 4);
    float4 b = *(const float4*)(g_IW1 + (size_t)d * AH + part * 4);
    float h0 = a.x + b.x, h1 = a.y + b.y, h2 = a.z + b.z, h3 = a.w + b.w;
    h0 = h0 >= 0.f ? h0 : 0.2f * h0;
    h1 = h1 >= 0.f ? h1 : 0.2f * h1;
    h2 = h2 >= 0.f ? h2 : 0.2f * h2;
    h3 = h3 >= 0.f ? h3 : 0.2f * h3;
    float pz = h0 * sW2[part*4] + h1 * sW2[part*4+1] + h2 * sW2[part*4+2] + h3 * sW2[part*4+3];
    pz += __shfl_down_sync(0xFFFFFFFFu, pz, 4, 8);
    pz += __shfl_down_sync(0xFFFFFFFFu, pz, 2, 8);
    pz += __shfl_down_sync(0xFFFFFFFFu, pz, 1, 8);

    float w = -1.0f;
    if (part == 0 && valid) {
        w = 1.0f / (1.0f + expf(-(pz + b2[0])));
        g_w[e] = w;
    }
    unsigned kb = __ballot_sync(0xFFFFFFFFu, w > THRESH);
    ull p = 0ULL;
    if (part == 0 && valid)
        p = (((ull)__float_as_uint(w)) << 32) | (ull)(0xFFFFFFFFu - (unsigned)e);
    { ull q = __shfl_down_sync(0xFFFFFFFFu, p, 16); if (q > p) p = q; }
    { ull q = __shfl_down_sync(0xFFFFFFFFu, p,  8); if (q > p) p = q; }
    if (lane == 0) {
        if (kb) atomicAdd(&blkkept, __popc(kb));
        atomicMax(&blkmax, p);
    }
    __syncthreads();
    if (tid == 0) {
        if (blkkept) atomicAdd(&g_kept, blkkept);
        else         atomicMax(&g_amax, blkmax);   // only matters if nothing kept anywhere
    }
}

__device__ __forceinline__ bool edge_kept(int e, float w) {
    if (g_kept > 0) return (w > THRESH);
    int am = (int)(0xFFFFFFFFu - (unsigned)(g_amax & 0xFFFFFFFFull));
    return (e == am);
}

// ---------------- K3: mask + denoised weights + histogram ----------------
__global__ void k_mask(const int* __restrict__ ei, float* __restrict__ wout, int E) {
    int e = blockIdx.x * blockDim.x + threadIdx.x;
    if (e >= E) return;
    float w = g_w[e];
    bool keep = edge_kept(e, w);
    wout[e] = keep ? w : 0.0f;
    if (keep) atomicAdd(&g_cnt[ei[E + e]], 1);
}

// ---------------- K4a: dinv from counts (deg = 1 + cnt, kept weight == 1) -----
__global__ void k_dinv() {
    int i = blockIdx.x * blockDim.x + threadIdx.x;
    if (i < NN) g_dinv[i] = rsqrtf(1.0f + (float)g_cnt[i]);
}

// ---------------- K4b: fast single-block scan ----------------
#define SCHUNK 40
__global__ void k_scan() {
    __shared__ int wsum[32];
    int t = threadIdx.x;
    int lane = t & 31, wid = t >> 5;
    int base = t * SCHUNK;
    int v[SCHUNK];
    int s = 0;
    #pragma unroll
    for (int i = 0; i < SCHUNK; i++) {
        int idx = base + i;
        v[i] = (idx < NN) ? g_cnt[idx] : 0;
        s += v[i];
    }
    int incl = s;
    #pragma unroll
    for (int o = 1; o < 32; o <<= 1) {
        int u = __shfl_up_sync(0xFFFFFFFFu, incl, o);
        if (lane >= o) incl += u;
    }
    if (lane == 31) wsum[wid] = incl;
    __syncthreads();
    if (wid == 0) {
        int ws = wsum[lane];
        #pragma unroll
        for (int o = 1; o < 32; o <<= 1) {
            int u = __shfl_up_sync(0xFFFFFFFFu, ws, o);
            if (lane >= o) ws += u;
        }
        wsum[lane] = ws;
    }
    __syncthreads();
    int excl = incl - s + (wid > 0 ? wsum[wid - 1] : 0);
    #pragma unroll
    for (int i = 0; i < SCHUNK; i++) {
        int idx = base + i;
        if (idx < NN) { g_off[idx] = excl; g_cur[idx] = excl; }
        excl += v[i];
    }
}

// ---------------- K5: CSR bucket fill ----------------
__global__ void k_fill(const int* __restrict__ ei, int E) {
    int e = blockIdx.x * blockDim.x + threadIdx.x;
    if (e >= E) return;
    float w = g_w[e];
    if (!edge_kept(e, w)) return;
    int s = ei[e], d = ei[E + e];
    int p = atomicAdd(&g_cur[d], 1);
    g_srcl[p] = s;
    g_coef[p] = g_dinv[s] * g_dinv[d];
}

// ---------------- K6: xw = concat(U,I) @ gcn_W, f32x2 packed FMA ----------------
// BM=128, BN=64, BK=16. 256 threads; per thread 4 rows (2 packed pairs) x 8 cols.
#define BM 128
#define BN 64
#define BK 16
#define APAD 2   // stride 130: conflict-free transpose stores, float2-aligned
__global__ void __launch_bounds__(256, 3) k_gemm(const float* __restrict__ U,
                                                 const float* __restrict__ I,
                                                 const float* __restrict__ W) {
    __shared__ float As[BK][BM + APAD];
    __shared__ float Bs[BK][BN];
    int m0 = blockIdx.x * BM, n0 = blockIdx.y * BN;
    int tid = threadIdx.x;
    int tr = tid >> 3;        // 0..31 -> 4 rows each
    int tc = tid & 7;         // 0..7  -> cols {tc*4..+3, 32+tc*4..+3}
    ull acc[2][8];
    #pragma unroll
    for (int p = 0; p < 2; p++)
        #pragma unroll
        for (int j = 0; j < 8; j++) acc[p][j] = 0ULL;

    for (int kk = 0; kk < HID; kk += BK) {
        // A: 128 rows x 16 k  (512 float4, 2 per thread), stored transposed
        #pragma unroll
        for (int rep = 0; rep < 2; rep++) {
            int id = rep * 256 + tid;
            int ml = id >> 2, c4 = (id & 3) * 4;
            int m = m0 + ml;
            const float* xr;
            if (m < NU)      xr = U + (size_t)m * HID;
            else if (m < NN) xr = I + (size_t)(m - NU) * HID;
            else             xr = U;  // safe dummy (last block tail)
            float4 va = *(const float4*)(xr + kk + c4);
            As[c4 + 0][ml] = va.x;
            As[c4 + 1][ml] = va.y;
            As[c4 + 2][ml] = va.z;
            As[c4 + 3][ml] = va.w;
        }
        // B: 16 x 64 (256 float4, 1 per thread)
        {
            int r = tid >> 4, c = (tid & 15) * 4;
            *(float4*)&Bs[r][c] = *(const float4*)(W + (size_t)(kk + r) * HID + n0 + c);
        }
        __syncthreads();
        #pragma unroll
        for (int k = 0; k < BK; k++) {
            float2 a0 = *(const float2*)&As[k][tr * 4];
            float2 a1 = *(const float2*)&As[k][tr * 4 + 2];
            ull av0 = pk2(a0.x, a0.y);
            ull av1 = pk2(a1.x, a1.y);
            float4 bl = *(const float4*)&Bs[k][tc * 4];
            float4 bh = *(const float4*)&Bs[k][32 + tc * 4];
            ull bb[8];
            bb[0] = pk2(bl.x, bl.x); bb[1] = pk2(bl.y, bl.y);
            bb[2] = pk2(bl.z, bl.z); bb[3] = pk2(bl.w, bl.w);
            bb[4] = pk2(bh.x, bh.x); bb[5] = pk2(bh.y, bh.y);
            bb[6] = pk2(bh.z, bh.z); bb[7] = pk2(bh.w, bh.w);
            #pragma unroll
            for (int j = 0; j < 8; j++) {
                ffma2(acc[0][j], av0, bb[j]);
                ffma2(acc[1][j], av1, bb[j]);
            }
        }
        __syncthreads();
    }
    // store: rows m0 + tr*4 + 2p + s, cols n0 + {tc*4, 32+tc*4}
    #pragma unroll
    for (int p = 0; p < 2; p++) {
        #pragma unroll
        for (int s = 0; s < 2; s++) {
            int m = m0 + tr * 4 + 2 * p + s;
            if (m >= NN) continue;
            float lo[4], hi[4];
            #pragma unroll
            for (int j = 0; j < 4; j++) {
                float2 v = *(float2*)&acc[p][j];
                lo[j] = s ? v.y : v.x;
                float2 u = *(float2*)&acc[p][4 + j];
                hi[j] = s ? u.y : u.x;
            }
            *(float4*)&g_xw[(size_t)m * HID + n0 + tc * 4]      = make_float4(lo[0], lo[1], lo[2], lo[3]);
            *(float4*)&g_xw[(size_t)m * HID + n0 + 32 + tc * 4] = make_float4(hi[0], hi[1], hi[2], hi[3]);
        }
    }
}

// ---------------- K7: per-node aggregate + self-loop + bias ----------------
__global__ void k_agg(const float* __restrict__ bias, float* __restrict__ out) {
    int n = blockIdx.x, t = threadIdx.x;
    __shared__ int   ss[64];
    __shared__ float sc[64];
    float di = g_dinv[n];
    float acc = g_xw[(size_t)n * HID + t] * (di * di) + bias[t];
    int beg = g_off[n], cnt = g_cnt[n];
    for (int base = 0; base < cnt; base += 64) {
        int nb = min(64, cnt - base);
        if (t < nb) {
            ss[t] = g_srcl[beg + base + t];
            sc[t] = g_coef[beg + base + t];
        }
        __syncthreads();
        for (int j = 0; j < nb; j++)
            acc += sc[j] * g_xw[(size_t)ss[j] * HID + t];
        __syncthreads();
    }
    out[(size_t)n * HID + t] = acc;
}

// ---------------- launch ----------------
extern "C" void kernel_launch(void* const* d_in, const int* in_sizes, int n_in,
                              void* d_out, int out_size) {
    const float* U  = (const float*)d_in[0];
    const float* I  = (const float*)d_in[1];
    const int*   ei = (const int*)  d_in[2];
    const float* W1 = (const float*)d_in[3];
    const float* b1 = (const float*)d_in[4];
    const float* W2 = (const float*)d_in[5];
    const float* b2 = (const float*)d_in[6];
    const float* GW = (const float*)d_in[7];
    const float* Gb = (const float*)d_in[8];
    int E = in_sizes[2] / 2;

    float* out  = (float*)d_out;
    float* wout = out + (size_t)NN * HID;

    k_init<<<(NN + 255) / 256, 256>>>();
    k_proj<<<(NN * 32 + 255) / 256, 256>>>(U, I, W1, b1);
    k_gemm<<<dim3((NN + BM - 1) / BM, HID / BN), 256>>>(U, I, GW);
    k_edge<<<((E + 3) / 4 * 32 + 255) / 256, 256>>>(ei, W2, b2, E);
    k_mask<<<(E + 255) / 256, 256>>>(ei, wout, E);
    k_dinv<<<(NN + 255) / 256, 256>>>();
    k_scan<<<1, 1024>>>();
    k_fill<<<(E + 255) / 256, 256>>>(ei, E);
    k_agg<<<NN, 256>>>(Gb, out);
}

// round 6
// speedup vs baseline: 1.7342x; 1.3258x over previous
#include <cuda_runtime.h>
#include <cuda_bf16.h>
#include <cstdint>

#define HID 256
#define AH  32
#define NU  10000
#define NI  30000
#define NN  40000
#define NE  500000
#define THRESH 0.8f

typedef unsigned long long ull;

// ---------------- device scratch ----------------
__device__ float g_UW1[NU * AH];
__device__ float g_IW1[NI * AH];
__device__ float g_w[NE];
__device__ float g_xw[(size_t)NN * HID];
__device__ float g_dinv[NN];
__device__ int   g_cnt[NN];
__device__ int   g_off[NN];
__device__ int   g_cur[NN];
__device__ int   g_srcl[NE];
__device__ float g_coef[NE];
__device__ ull   g_amax;
__device__ int   g_kept;
__device__ __align__(16) __nv_bfloat16 g_Bhi[HID * HID];  // W^T hi  [n][k]
__device__ __align__(16) __nv_bfloat16 g_Blo[HID * HID];  // W^T lo  [n][k]

// ---------------- helpers ----------------
__device__ __forceinline__ uint32_t s2u(const void* p) {
    uint32_t a;
    asm("{ .reg .u64 t; cvta.to.shared.u64 t, %1; cvt.u32.u64 %0, t; }" : "=r"(a) : "l"(p));
    return a;
}
__device__ __forceinline__ void ldsm4(uint32_t* r, uint32_t addr) {
    asm volatile("ldmatrix.sync.aligned.m8n8.x4.shared.b16 {%0,%1,%2,%3}, [%4];"
                 : "=r"(r[0]), "=r"(r[1]), "=r"(r[2]), "=r"(r[3]) : "r"(addr));
}
__device__ __forceinline__ void mma16816(float* c, const uint32_t* a, const uint32_t* b) {
    asm volatile("mma.sync.aligned.m16n8k16.row.col.f32.bf16.bf16.f32 "
                 "{%0,%1,%2,%3}, {%4,%5,%6,%7}, {%8,%9}, {%0,%1,%2,%3};"
                 : "+f"(c[0]), "+f"(c[1]), "+f"(c[2]), "+f"(c[3])
                 : "r"(a[0]), "r"(a[1]), "r"(a[2]), "r"(a[3]), "r"(b[0]), "r"(b[1]));
}

// ---------------- K0: reset ----------------
__global__ void k_init() {
    int i = blockIdx.x * blockDim.x + threadIdx.x;
    if (i < NN) g_cnt[i] = 0;
    if (i == 0) { g_amax = 0ULL; g_kept = 0; }
}

// ---------------- K_prepW: transpose + bf16 hi/lo split of gcn_W ----------------
__global__ void k_prepW(const float* __restrict__ W) {
    int i = blockIdx.x * blockDim.x + threadIdx.x;   // 65536
    int n = i & 255, k = i >> 8;
    float v = W[k * HID + n];
    __nv_bfloat16 h = __float2bfloat16(v);
    g_Bhi[n * HID + k] = h;
    g_Blo[n * HID + k] = __float2bfloat16(v - __bfloat162float(h));
}

// ---------------- K1: tiled node projection  P = X @ Wp (+b) ----------------
__global__ void k_projT(const float* __restrict__ X, const float* __restrict__ Wp,
                        const float* __restrict__ b1, float* __restrict__ P, int nrows) {
    __shared__ float Xs[32][68];
    __shared__ float Ws[32][32];
    int m0 = blockIdx.x * 64;
    int tid = threadIdx.x;
    int tr = tid >> 4, tc = tid & 15;
    float acc[4][2] = {};
    for (int kc = 0; kc < HID; kc += 32) {
        for (int i = tid; i < 512; i += 256) {
            int r = i >> 3, q = i & 7;
            int m = m0 + r; if (m >= nrows) m = nrows - 1;
            float4 v = *(const float4*)(X + (size_t)m * HID + kc + q * 4);
            Xs[q*4+0][r] = v.x; Xs[q*4+1][r] = v.y;
            Xs[q*4+2][r] = v.z; Xs[q*4+3][r] = v.w;
        }
        {
            int r = tid >> 3, q = tid & 7;
            *(float4*)&Ws[r][q * 4] = *(const float4*)(Wp + (size_t)(kc + r) * AH + q * 4);
        }
        __syncthreads();
        #pragma unroll
        for (int k = 0; k < 32; k++) {
            float4 a = *(const float4*)&Xs[k][tr * 4];
            float2 b = *(const float2*)&Ws[k][tc * 2];
            acc[0][0] += a.x * b.x; acc[0][1] += a.x * b.y;
            acc[1][0] += a.y * b.x; acc[1][1] += a.y * b.y;
            acc[2][0] += a.z * b.x; acc[2][1] += a.z * b.y;
            acc[3][0] += a.w * b.x; acc[3][1] += a.w * b.y;
        }
        __syncthreads();
    }
    float bb0 = b1 ? b1[tc * 2] : 0.f, bb1 = b1 ? b1[tc * 2 + 1] : 0.f;
    #pragma unroll
    for (int i = 0; i < 4; i++) {
        int m = m0 + tr * 4 + i;
        if (m < nrows) {
            P[(size_t)m * AH + tc * 2]     = acc[i][0] + bb0;
            P[(size_t)m * AH + tc * 2 + 1] = acc[i][1] + bb1;
        }
    }
}

// ---------------- K2: edge attention (8 lanes per edge) ----------------
__global__ void k_edge(const int* __restrict__ ei, const float* __restrict__ W2,
                       const float* __restrict__ b2, int E) {
    __shared__ float sW2[AH];
    __shared__ ull   blkmax;
    __shared__ int   blkkept;
    int tid = threadIdx.x;
    if (tid < AH) sW2[tid] = W2[tid];
    if (tid == 0) { blkmax = 0ULL; blkkept = 0; }
    __syncthreads();

    int lane = tid & 31;
    int gw = (blockIdx.x * blockDim.x + tid) >> 5;
    int sub = lane >> 3, part = lane & 7;
    int e = gw * 4 + sub;
    bool valid = e < E;
    int s = 0, d = 0;
    if (valid) { s = ei[e]; d = ei[E + e]; }

    float4 a = *(const float4*)(g_UW1 + (size_t)s * AH + part * 4);
    float4 b = *(const float4*)(g_IW1 + (size_t)d * AH + part * 4);
    float h0 = a.x + b.x, h1 = a.y + b.y, h2 = a.z + b.z, h3 = a.w + b.w;
    h0 = h0 >= 0.f ? h0 : 0.2f * h0;
    h1 = h1 >= 0.f ? h1 : 0.2f * h1;
    h2 = h2 >= 0.f ? h2 : 0.2f * h2;
    h3 = h3 >= 0.f ? h3 : 0.2f * h3;
    float pz = h0 * sW2[part*4] + h1 * sW2[part*4+1] + h2 * sW2[part*4+2] + h3 * sW2[part*4+3];
    pz += __shfl_down_sync(0xFFFFFFFFu, pz, 4, 8);
    pz += __shfl_down_sync(0xFFFFFFFFu, pz, 2, 8);
    pz += __shfl_down_sync(0xFFFFFFFFu, pz, 1, 8);

    float w = -1.0f;
    if (part == 0 && valid) {
        w = 1.0f / (1.0f + expf(-(pz + b2[0])));
        g_w[e] = w;
    }
    unsigned kb = __ballot_sync(0xFFFFFFFFu, w > THRESH);
    ull p = 0ULL;
    if (part == 0 && valid)
        p = (((ull)__float_as_uint(w)) << 32) | (ull)(0xFFFFFFFFu - (unsigned)e);
    { ull q = __shfl_down_sync(0xFFFFFFFFu, p, 16); if (q > p) p = q; }
    { ull q = __shfl_down_sync(0xFFFFFFFFu, p,  8); if (q > p) p = q; }
    if (lane == 0) {
        if (kb) atomicAdd(&blkkept, __popc(kb));
        atomicMax(&blkmax, p);
    }
    __syncthreads();
    if (tid == 0) {
        if (blkkept) atomicAdd(&g_kept, blkkept);
        else         atomicMax(&g_amax, blkmax);
    }
}

__device__ __forceinline__ bool edge_kept(int e, float w) {
    if (g_kept > 0) return (w > THRESH);
    int am = (int)(0xFFFFFFFFu - (unsigned)(g_amax & 0xFFFFFFFFull));
    return (e == am);
}

// ---------------- K3: mask + denoised weights + histogram ----------------
__global__ void k_mask(const int* __restrict__ ei, float* __restrict__ wout, int E) {
    int e = blockIdx.x * blockDim.x + threadIdx.x;
    if (e >= E) return;
    float w = g_w[e];
    bool keep = edge_kept(e, w);
    wout[e] = keep ? w : 0.0f;
    if (keep) atomicAdd(&g_cnt[ei[E + e]], 1);
}

// ---------------- K4a: dinv (deg = 1 + cnt) ----------------
__global__ void k_dinv() {
    int i = blockIdx.x * blockDim.x + threadIdx.x;
    if (i < NN) g_dinv[i] = rsqrtf(1.0f + (float)g_cnt[i]);
}

// ---------------- K4b: single-block scan ----------------
#define SCHUNK 40
__global__ void k_scan() {
    __shared__ int wsum[32];
    int t = threadIdx.x;
    int lane = t & 31, wid = t >> 5;
    int base = t * SCHUNK;
    int v[SCHUNK];
    int s = 0;
    #pragma unroll
    for (int i = 0; i < SCHUNK; i++) {
        int idx = base + i;
        v[i] = (idx < NN) ? g_cnt[idx] : 0;
        s += v[i];
    }
    int incl = s;
    #pragma unroll
    for (int o = 1; o < 32; o <<= 1) {
        int u = __shfl_up_sync(0xFFFFFFFFu, incl, o);
        if (lane >= o) incl += u;
    }
    if (lane == 31) wsum[wid] = incl;
    __syncthreads();
    if (wid == 0) {
        int ws = wsum[lane];
        #pragma unroll
        for (int o = 1; o < 32; o <<= 1) {
            int u = __shfl_up_sync(0xFFFFFFFFu, ws, o);
            if (lane >= o) ws += u;
        }
        wsum[lane] = ws;
    }
    __syncthreads();
    int excl = incl - s + (wid > 0 ? wsum[wid - 1] : 0);
    #pragma unroll
    for (int i = 0; i < SCHUNK; i++) {
        int idx = base + i;
        if (idx < NN) { g_off[idx] = excl; g_cur[idx] = excl; }
        excl += v[i];
    }
}

// ---------------- K5: CSR bucket fill ----------------
__global__ void k_fill(const int* __restrict__ ei, int E) {
    int e = blockIdx.x * blockDim.x + threadIdx.x;
    if (e >= E) return;
    float w = g_w[e];
    if (!edge_kept(e, w)) return;
    int s = ei[e], d = ei[E + e];
    int p = atomicAdd(&g_cur[d], 1);
    g_srcl[p] = s;
    g_coef[p] = g_dinv[s] * g_dinv[d];
}

// ---------------- K6: xw = concat(U,I) @ gcn_W via HMMA bf16 3-pass ----------------
// CTA tile 128x128, K-chunks of 32. 8 warps (2x4), warp tile 64x32.
#define KC   32
#define ASTR 40   // bf16 per smem row (80 B): 20-bank stride, conflict-free ldmatrix
__global__ void __launch_bounds__(256, 2) k_gemm_hmma(const float* __restrict__ U,
                                                      const float* __restrict__ I) {
    __shared__ __nv_bfloat16 Ah[128 * ASTR], Al[128 * ASTR];
    __shared__ __nv_bfloat16 Bh[128 * ASTR], Bl[128 * ASTR];
    int tid = threadIdx.x, warp = tid >> 5, lane = tid & 31;
    int m0 = blockIdx.x * 128, n0 = blockIdx.y * 128;
    int wm = warp >> 2, wn = warp & 3;          // warp tile: rows wm*64, cols wn*32

    // ldmatrix lane base offsets (bytes)
    int g = lane >> 3, r8 = lane & 7;
    uint32_t aoff = (uint32_t)((wm * 64 + (g & 1) * 8 + r8) * (ASTR * 2) + (g >> 1) * 16);
    uint32_t boff = (uint32_t)((wn * 32 + (g >> 1) * 8 + r8) * (ASTR * 2) + (g & 1) * 16);
    uint32_t sAh = s2u(Ah) + aoff, sAl = s2u(Al) + aoff;
    uint32_t sBh = s2u(Bh) + boff, sBl = s2u(Bl) + boff;

    float acc[4][4][4];
    #pragma unroll
    for (int i = 0; i < 4; i++)
        #pragma unroll
        for (int j = 0; j < 4; j++)
            #pragma unroll
            for (int q = 0; q < 4; q++) acc[i][j][q] = 0.f;

    for (int kc = 0; kc < HID; kc += KC) {
        if (kc) __syncthreads();
        // A: 128 rows x 32 k fp32 -> hi/lo bf16
        for (int i = tid; i < 1024; i += 256) {
            int r = i >> 3, q = i & 7;
            int m = m0 + r; if (m >= NN) m = NN - 1;
            const float* xr = (m < NU) ? U + (size_t)m * HID : I + (size_t)(m - NU) * HID;
            float4 v = *(const float4*)(xr + kc + q * 4);
            __nv_bfloat16 h0 = __float2bfloat16(v.x), h1 = __float2bfloat16(v.y);
            __nv_bfloat16 h2 = __float2bfloat16(v.z), h3 = __float2bfloat16(v.w);
            __nv_bfloat16 l0 = __float2bfloat16(v.x - __bfloat162float(h0));
            __nv_bfloat16 l1 = __float2bfloat16(v.y - __bfloat162float(h1));
            __nv_bfloat16 l2 = __float2bfloat16(v.z - __bfloat162float(h2));
            __nv_bfloat16 l3 = __float2bfloat16(v.w - __bfloat162float(h3));
            __nv_bfloat162 hp0, hp1, lp0, lp1;
            hp0.x = h0; hp0.y = h1; hp1.x = h2; hp1.y = h3;
            lp0.x = l0; lp0.y = l1; lp1.x = l2; lp1.y = l3;
            *(uint2*)&Ah[r * ASTR + q * 4] = make_uint2(*(uint32_t*)&hp0, *(uint32_t*)&hp1);
            *(uint2*)&Al[r * ASTR + q * 4] = make_uint2(*(uint32_t*)&lp0, *(uint32_t*)&lp1);
        }
        // B: 128 n-rows x 32 k bf16 (precomputed W^T hi/lo)
        for (int i = tid; i < 512; i += 256) {
            int r = i >> 2, q = i & 3;
            const __nv_bfloat16* sh = g_Bhi + (size_t)(n0 + r) * HID + kc + q * 8;
            const __nv_bfloat16* sl = g_Blo + (size_t)(n0 + r) * HID + kc + q * 8;
            *(uint4*)&Bh[r * ASTR + q * 8] = *(const uint4*)sh;
            *(uint4*)&Bl[r * ASTR + q * 8] = *(const uint4*)sl;
        }
        __syncthreads();

        #pragma unroll
        for (int ks = 0; ks < 2; ks++) {
            uint32_t a[4][4], bh[2][4], bl[2][4];
            uint32_t kb = (uint32_t)(ks * 32);
            #pragma unroll
            for (int mf = 0; mf < 4; mf++) ldsm4(a[mf], sAh + mf * (16 * ASTR * 2) + kb);
            #pragma unroll
            for (int j = 0; j < 2; j++) ldsm4(bh[j], sBh + j * (16 * ASTR * 2) + kb);
            #pragma unroll
            for (int j = 0; j < 2; j++) ldsm4(bl[j], sBl + j * (16 * ASTR * 2) + kb);
            #pragma unroll
            for (int mf = 0; mf < 4; mf++)
                #pragma unroll
                for (int j = 0; j < 2; j++) {
                    mma16816(acc[mf][j*2+0], a[mf], &bh[j][0]);
                    mma16816(acc[mf][j*2+1], a[mf], &bh[j][2]);
                    mma16816(acc[mf][j*2+0], a[mf], &bl[j][0]);
                    mma16816(acc[mf][j*2+1], a[mf], &bl[j][2]);
                }
            #pragma unroll
            for (int mf = 0; mf < 4; mf++) ldsm4(a[mf], sAl + mf * (16 * ASTR * 2) + kb);
            #pragma unroll
            for (int mf = 0; mf < 4; mf++)
                #pragma unroll
                for (int j = 0; j < 2; j++) {
                    mma16816(acc[mf][j*2+0], a[mf], &bh[j][0]);
                    mma16816(acc[mf][j*2+1], a[mf], &bh[j][2]);
                }
        }
    }

    // epilogue: c frag -> g_xw
    int qr = lane >> 2, qc = (lane & 3) * 2;
    #pragma unroll
    for (int mf = 0; mf < 4; mf++) {
        int mrow = m0 + wm * 64 + mf * 16 + qr;
        #pragma unroll
        for (int nf = 0; nf < 4; nf++) {
            int col = n0 + wn * 32 + nf * 8 + qc;
            if (mrow < NN)
                *(float2*)&g_xw[(size_t)mrow * HID + col] = make_float2(acc[mf][nf][0], acc[mf][nf][1]);
            if (mrow + 8 < NN)
                *(float2*)&g_xw[(size_t)(mrow + 8) * HID + col] = make_float2(acc[mf][nf][2], acc[mf][nf][3]);
        }
    }
}

// ---------------- K7: per-node aggregate + self-loop + bias ----------------
__global__ void k_agg(const float* __restrict__ bias, float* __restrict__ out) {
    int n = blockIdx.x, t = threadIdx.x;
    __shared__ int   ss[64];
    __shared__ float sc[64];
    float di = g_dinv[n];
    float acc = g_xw[(size_t)n * HID + t] * (di * di) + bias[t];
    int beg = g_off[n], cnt = g_cnt[n];
    for (int base = 0; base < cnt; base += 64) {
        int nb = min(64, cnt - base);
        if (t < nb) {
            ss[t] = g_srcl[beg + base + t];
            sc[t] = g_coef[beg + base + t];
        }
        __syncthreads();
        for (int j = 0; j < nb; j++)
            acc += sc[j] * g_xw[(size_t)ss[j] * HID + t];
        __syncthreads();
    }
    out[(size_t)n * HID + t] = acc;
}

// ---------------- launch ----------------
extern "C" void kernel_launch(void* const* d_in, const int* in_sizes, int n_in,
                              void* d_out, int out_size) {
    const float* U  = (const float*)d_in[0];
    const float* I  = (const float*)d_in[1];
    const int*   ei = (const int*)  d_in[2];
    const float* W1 = (const float*)d_in[3];
    const float* b1 = (const float*)d_in[4];
    const float* W2 = (const float*)d_in[5];
    const float* b2 = (const float*)d_in[6];
    const float* GW = (const float*)d_in[7];
    const float* Gb = (const float*)d_in[8];
    int E = in_sizes[2] / 2;

    float* out  = (float*)d_out;
    float* wout = out + (size_t)NN * HID;

    float* UW1p; cudaGetSymbolAddress((void**)&UW1p, g_UW1);
    float* IW1p; cudaGetSymbolAddress((void**)&IW1p, g_IW1);

    k_init<<<(NN + 255) / 256, 256>>>();
    k_prepW<<<HID * HID / 256, 256>>>(GW);
    k_projT<<<(NU + 63) / 64, 256>>>(U, W1,            b1,      UW1p, NU);
    k_projT<<<(NI + 63) / 64, 256>>>(I, W1 + HID * AH, nullptr, IW1p, NI);
    k_gemm_hmma<<<dim3((NN + 127) / 128, HID / 128), 256>>>(U, I);
    k_edge<<<((E + 3) / 4 * 32 + 255) / 256, 256>>>(ei, W2, b2, E);
    k_mask<<<(E + 255) / 256, 256>>>(ei, wout, E);
    k_dinv<<<(NN + 255) / 256, 256>>>();
    k_scan<<<1, 1024>>>();
    k_fill<<<(E + 255) / 256, 256>>>(ei, E);
    k_agg<<<NN, 256>>>(Gb, out);
}

// round 7
// speedup vs baseline: 1.8587x; 1.0718x over previous
#include <cuda_runtime.h>
#include <cuda_bf16.h>
#include <cstdint>

#define HID 256
#define AH  32
#define NU  10000
#define NI  30000
#define NN  40000
#define NE  500000
#define THRESH 0.8f

typedef unsigned long long ull;

// ---------------- device scratch ----------------
__device__ float g_UW1[NU * AH];
__device__ float g_IW1[NI * AH];
__device__ float g_w[NE];
__device__ float g_xw[(size_t)NN * HID];
__device__ float g_dinv[NN];
__device__ int   g_cnt[NN];
__device__ int   g_off[NN];
__device__ int   g_cur[NN];
__device__ int   g_srcl[NE];
__device__ float g_coef[NE];
__device__ ull   g_amax;
__device__ int   g_kept;
__device__ __align__(16) __nv_bfloat16 g_Bhi[HID * HID];  // W^T hi  [n][k]
__device__ __align__(16) __nv_bfloat16 g_Blo[HID * HID];  // W^T lo  [n][k]

// ---------------- helpers ----------------
__device__ __forceinline__ uint32_t s2u(const void* p) {
    uint32_t a;
    asm("{ .reg .u64 t; cvta.to.shared.u64 t, %1; cvt.u32.u64 %0, t; }" : "=r"(a) : "l"(p));
    return a;
}
__device__ __forceinline__ void ldsm4(uint32_t* r, uint32_t addr) {
    asm volatile("ldmatrix.sync.aligned.m8n8.x4.shared.b16 {%0,%1,%2,%3}, [%4];"
                 : "=r"(r[0]), "=r"(r[1]), "=r"(r[2]), "=r"(r[3]) : "r"(addr));
}
__device__ __forceinline__ void mma16816(float* c, const uint32_t* a, const uint32_t* b) {
    asm volatile("mma.sync.aligned.m16n8k16.row.col.f32.bf16.bf16.f32 "
                 "{%0,%1,%2,%3}, {%4,%5,%6,%7}, {%8,%9}, {%0,%1,%2,%3};"
                 : "+f"(c[0]), "+f"(c[1]), "+f"(c[2]), "+f"(c[3])
                 : "r"(a[0]), "r"(a[1]), "r"(a[2]), "r"(a[3]), "r"(b[0]), "r"(b[1]));
}

// ---------------- K0: reset ----------------
__global__ void k_init() {
    int i = blockIdx.x * blockDim.x + threadIdx.x;
    if (i < NN) g_cnt[i] = 0;
    if (i == 0) { g_amax = 0ULL; g_kept = 0; }
}

// ---------------- K_prepW: transpose + bf16 hi/lo split of gcn_W ----------------
__global__ void k_prepW(const float* __restrict__ W) {
    int i = blockIdx.x * blockDim.x + threadIdx.x;   // 65536
    int n = i & 255, k = i >> 8;
    float v = W[k * HID + n];
    __nv_bfloat16 h = __float2bfloat16(v);
    g_Bhi[n * HID + k] = h;
    g_Blo[n * HID + k] = __float2bfloat16(v - __bfloat162float(h));
}

// ---------------- K1: merged node projection (user + item segments) ----------------
#define UBLKS ((NU + 63) / 64)   // 157
#define IBLKS ((NI + 63) / 64)   // 469
__global__ void k_projA(const float* __restrict__ U, const float* __restrict__ I,
                        const float* __restrict__ W1, const float* __restrict__ b1) {
    __shared__ float Xs[32][68];
    __shared__ float Ws[32][32];
    const float* X; const float* Wp; const float* bv; float* P;
    int nrows, m0;
    if (blockIdx.x < UBLKS) {
        X = U;  Wp = W1;            bv = b1;      P = g_UW1; nrows = NU;
        m0 = blockIdx.x * 64;
    } else {
        X = I;  Wp = W1 + HID * AH; bv = nullptr; P = g_IW1; nrows = NI;
        m0 = (blockIdx.x - UBLKS) * 64;
    }
    int tid = threadIdx.x;
    int tr = tid >> 4, tc = tid & 15;
    float acc[4][2] = {};
    for (int kc = 0; kc < HID; kc += 32) {
        for (int i = tid; i < 512; i += 256) {
            int r = i >> 3, q = i & 7;
            int m = m0 + r; if (m >= nrows) m = nrows - 1;
            float4 v = *(const float4*)(X + (size_t)m * HID + kc + q * 4);
            Xs[q*4+0][r] = v.x; Xs[q*4+1][r] = v.y;
            Xs[q*4+2][r] = v.z; Xs[q*4+3][r] = v.w;
        }
        {
            int r = tid >> 3, q = tid & 7;
            *(float4*)&Ws[r][q * 4] = *(const float4*)(Wp + (size_t)(kc + r) * AH + q * 4);
        }
        __syncthreads();
        #pragma unroll
        for (int k = 0; k < 32; k++) {
            float4 a = *(const float4*)&Xs[k][tr * 4];
            float2 b = *(const float2*)&Ws[k][tc * 2];
            acc[0][0] += a.x * b.x; acc[0][1] += a.x * b.y;
            acc[1][0] += a.y * b.x; acc[1][1] += a.y * b.y;
            acc[2][0] += a.z * b.x; acc[2][1] += a.z * b.y;
            acc[3][0] += a.w * b.x; acc[3][1] += a.w * b.y;
        }
        __syncthreads();
    }
    float bb0 = bv ? bv[tc * 2] : 0.f, bb1 = bv ? bv[tc * 2 + 1] : 0.f;
    #pragma unroll
    for (int i = 0; i < 4; i++) {
        int m = m0 + tr * 4 + i;
        if (m < nrows) {
            P[(size_t)m * AH + tc * 2]     = acc[i][0] + bb0;
            P[(size_t)m * AH + tc * 2 + 1] = acc[i][1] + bb1;
        }
    }
}

// ---------------- K2: edge attention (8 lanes per edge) ----------------
__global__ void k_edge(const int* __restrict__ ei, const float* __restrict__ W2,
                       const float* __restrict__ b2, int E) {
    __shared__ float sW2[AH];
    __shared__ ull   blkmax;
    __shared__ int   blkkept;
    int tid = threadIdx.x;
    if (tid < AH) sW2[tid] = W2[tid];
    if (tid == 0) { blkmax = 0ULL; blkkept = 0; }
    __syncthreads();

    int lane = tid & 31;
    int gw = (blockIdx.x * blockDim.x + tid) >> 5;
    int sub = lane >> 3, part = lane & 7;
    int e = gw * 4 + sub;
    bool valid = e < E;
    int s = 0, d = 0;
    if (valid) { s = ei[e]; d = ei[E + e]; }

    float4 a = *(const float4*)(g_UW1 + (size_t)s * AH + part * 4);
    float4 b = *(const float4*)(g_IW1 + (size_t)d * AH + part * 4);
    float h0 = a.x + b.x, h1 = a.y + b.y, h2 = a.z + b.z, h3 = a.w + b.w;
    h0 = h0 >= 0.f ? h0 : 0.2f * h0;
    h1 = h1 >= 0.f ? h1 : 0.2f * h1;
    h2 = h2 >= 0.f ? h2 : 0.2f * h2;
    h3 = h3 >= 0.f ? h3 : 0.2f * h3;
    float pz = h0 * sW2[part*4] + h1 * sW2[part*4+1] + h2 * sW2[part*4+2] + h3 * sW2[part*4+3];
    pz += __shfl_down_sync(0xFFFFFFFFu, pz, 4, 8);
    pz += __shfl_down_sync(0xFFFFFFFFu, pz, 2, 8);
    pz += __shfl_down_sync(0xFFFFFFFFu, pz, 1, 8);

    float w = -1.0f;
    if (part == 0 && valid) {
        w = 1.0f / (1.0f + expf(-(pz + b2[0])));
        g_w[e] = w;
    }
    unsigned kb = __ballot_sync(0xFFFFFFFFu, w > THRESH);
    ull p = 0ULL;
    if (part == 0 && valid)
        p = (((ull)__float_as_uint(w)) << 32) | (ull)(0xFFFFFFFFu - (unsigned)e);
    { ull q = __shfl_down_sync(0xFFFFFFFFu, p, 16); if (q > p) p = q; }
    { ull q = __shfl_down_sync(0xFFFFFFFFu, p,  8); if (q > p) p = q; }
    if (lane == 0) {
        if (kb) atomicAdd(&blkkept, __popc(kb));
        atomicMax(&blkmax, p);
    }
    __syncthreads();
    if (tid == 0) {
        if (blkkept) atomicAdd(&g_kept, blkkept);
        else         atomicMax(&g_amax, blkmax);
    }
}

__device__ __forceinline__ bool edge_kept(int e, float w) {
    if (g_kept > 0) return (w > THRESH);
    int am = (int)(0xFFFFFFFFu - (unsigned)(g_amax & 0xFFFFFFFFull));
    return (e == am);
}

// ---------------- K3: mask + denoised weights + histogram ----------------
__global__ void k_mask(const int* __restrict__ ei, float* __restrict__ wout, int E) {
    int e = blockIdx.x * blockDim.x + threadIdx.x;
    if (e >= E) return;
    float w = g_w[e];
    bool keep = edge_kept(e, w);
    wout[e] = keep ? w : 0.0f;
    if (keep) atomicAdd(&g_cnt[ei[E + e]], 1);
}

// ---------------- K4a: dinv (deg = 1 + cnt) ----------------
__global__ void k_dinv() {
    int i = blockIdx.x * blockDim.x + threadIdx.x;
    if (i < NN) g_dinv[i] = rsqrtf(1.0f + (float)g_cnt[i]);
}

// ---------------- K4b: single-block scan ----------------
#define SCHUNK 40
__global__ void k_scan() {
    __shared__ int wsum[32];
    int t = threadIdx.x;
    int lane = t & 31, wid = t >> 5;
    int base = t * SCHUNK;
    int v[SCHUNK];
    int s = 0;
    #pragma unroll
    for (int i = 0; i < SCHUNK; i++) {
        int idx = base + i;
        v[i] = (idx < NN) ? g_cnt[idx] : 0;
        s += v[i];
    }
    int incl = s;
    #pragma unroll
    for (int o = 1; o < 32; o <<= 1) {
        int u = __shfl_up_sync(0xFFFFFFFFu, incl, o);
        if (lane >= o) incl += u;
    }
    if (lane == 31) wsum[wid] = incl;
    __syncthreads();
    if (wid == 0) {
        int ws = wsum[lane];
        #pragma unroll
        for (int o = 1; o < 32; o <<= 1) {
            int u = __shfl_up_sync(0xFFFFFFFFu, ws, o);
            if (lane >= o) ws += u;
        }
        wsum[lane] = ws;
    }
    __syncthreads();
    int excl = incl - s + (wid > 0 ? wsum[wid - 1] : 0);
    #pragma unroll
    for (int i = 0; i < SCHUNK; i++) {
        int idx = base + i;
        if (idx < NN) { g_off[idx] = excl; g_cur[idx] = excl; }
        excl += v[i];
    }
}

// ---------------- K5: CSR bucket fill ----------------
__global__ void k_fill(const int* __restrict__ ei, int E) {
    int e = blockIdx.x * blockDim.x + threadIdx.x;
    if (e >= E) return;
    float w = g_w[e];
    if (!edge_kept(e, w)) return;
    int s = ei[e], d = ei[E + e];
    int p = atomicAdd(&g_cur[d], 1);
    g_srcl[p] = s;
    g_coef[p] = g_dinv[s] * g_dinv[d];
}

// ---------------- K6: xw = concat(U,I) @ gcn_W via HMMA bf16 3-pass ----------------
#define KC   32
#define ASTR 40
__global__ void __launch_bounds__(256, 2) k_gemm_hmma(const float* __restrict__ U,
                                                      const float* __restrict__ I) {
    __shared__ __nv_bfloat16 Ah[128 * ASTR], Al[128 * ASTR];
    __shared__ __nv_bfloat16 Bh[128 * ASTR], Bl[128 * ASTR];
    int tid = threadIdx.x, warp = tid >> 5, lane = tid & 31;
    int m0 = blockIdx.x * 128, n0 = blockIdx.y * 128;
    int wm = warp >> 2, wn = warp & 3;

    int g = lane >> 3, r8 = lane & 7;
    uint32_t aoff = (uint32_t)((wm * 64 + (g & 1) * 8 + r8) * (ASTR * 2) + (g >> 1) * 16);
    uint32_t boff = (uint32_t)((wn * 32 + (g >> 1) * 8 + r8) * (ASTR * 2) + (g & 1) * 16);
    uint32_t sAh = s2u(Ah) + aoff, sAl = s2u(Al) + aoff;
    uint32_t sBh = s2u(Bh) + boff, sBl = s2u(Bl) + boff;

    float acc[4][4][4];
    #pragma unroll
    for (int i = 0; i < 4; i++)
        #pragma unroll
        for (int j = 0; j < 4; j++)
            #pragma unroll
            for (int q = 0; q < 4; q++) acc[i][j][q] = 0.f;

    for (int kc = 0; kc < HID; kc += KC) {
        if (kc) __syncthreads();
        for (int i = tid; i < 1024; i += 256) {
            int r = i >> 3, q = i & 7;
            int m = m0 + r; if (m >= NN) m = NN - 1;
            const float* xr = (m < NU) ? U + (size_t)m * HID : I + (size_t)(m - NU) * HID;
            float4 v = *(const float4*)(xr + kc + q * 4);
            __nv_bfloat16 h0 = __float2bfloat16(v.x), h1 = __float2bfloat16(v.y);
            __nv_bfloat16 h2 = __float2bfloat16(v.z), h3 = __float2bfloat16(v.w);
            __nv_bfloat16 l0 = __float2bfloat16(v.x - __bfloat162float(h0));
            __nv_bfloat16 l1 = __float2bfloat16(v.y - __bfloat162float(h1));
            __nv_bfloat16 l2 = __float2bfloat16(v.z - __bfloat162float(h2));
            __nv_bfloat16 l3 = __float2bfloat16(v.w - __bfloat162float(h3));
            __nv_bfloat162 hp0, hp1, lp0, lp1;
            hp0.x = h0; hp0.y = h1; hp1.x = h2; hp1.y = h3;
            lp0.x = l0; lp0.y = l1; lp1.x = l2; lp1.y = l3;
            *(uint2*)&Ah[r * ASTR + q * 4] = make_uint2(*(uint32_t*)&hp0, *(uint32_t*)&hp1);
            *(uint2*)&Al[r * ASTR + q * 4] = make_uint2(*(uint32_t*)&lp0, *(uint32_t*)&lp1);
        }
        for (int i = tid; i < 512; i += 256) {
            int r = i >> 2, q = i & 3;
            const __nv_bfloat16* sh = g_Bhi + (size_t)(n0 + r) * HID + kc + q * 8;
            const __nv_bfloat16* sl = g_Blo + (size_t)(n0 + r) * HID + kc + q * 8;
            *(uint4*)&Bh[r * ASTR + q * 8] = *(const uint4*)sh;
            *(uint4*)&Bl[r * ASTR + q * 8] = *(const uint4*)sl;
        }
        __syncthreads();

        #pragma unroll
        for (int ks = 0; ks < 2; ks++) {
            uint32_t a[4][4], bh[2][4], bl[2][4];
            uint32_t kb = (uint32_t)(ks * 32);
            #pragma unroll
            for (int mf = 0; mf < 4; mf++) ldsm4(a[mf], sAh + mf * (16 * ASTR * 2) + kb);
            #pragma unroll
            for (int j = 0; j < 2; j++) ldsm4(bh[j], sBh + j * (16 * ASTR * 2) + kb);
            #pragma unroll
            for (int j = 0; j < 2; j++) ldsm4(bl[j], sBl + j * (16 * ASTR * 2) + kb);
            #pragma unroll
            for (int mf = 0; mf < 4; mf++)
                #pragma unroll
                for (int j = 0; j < 2; j++) {
                    mma16816(acc[mf][j*2+0], a[mf], &bh[j][0]);
                    mma16816(acc[mf][j*2+1], a[mf], &bh[j][2]);
                    mma16816(acc[mf][j*2+0], a[mf], &bl[j][0]);
                    mma16816(acc[mf][j*2+1], a[mf], &bl[j][2]);
                }
            #pragma unroll
            for (int mf = 0; mf < 4; mf++) ldsm4(a[mf], sAl + mf * (16 * ASTR * 2) + kb);
            #pragma unroll
            for (int mf = 0; mf < 4; mf++)
                #pragma unroll
                for (int j = 0; j < 2; j++) {
                    mma16816(acc[mf][j*2+0], a[mf], &bh[j][0]);
                    mma16816(acc[mf][j*2+1], a[mf], &bh[j][2]);
                }
        }
    }

    int qr = lane >> 2, qc = (lane & 3) * 2;
    #pragma unroll
    for (int mf = 0; mf < 4; mf++) {
        int mrow = m0 + wm * 64 + mf * 16 + qr;
        #pragma unroll
        for (int nf = 0; nf < 4; nf++) {
            int col = n0 + wn * 32 + nf * 8 + qc;
            if (mrow < NN)
                *(float2*)&g_xw[(size_t)mrow * HID + col] = make_float2(acc[mf][nf][0], acc[mf][nf][1]);
            if (mrow + 8 < NN)
                *(float2*)&g_xw[(size_t)(mrow + 8) * HID + col] = make_float2(acc[mf][nf][2], acc[mf][nf][3]);
        }
    }
}

// ---------------- K7: per-node aggregate + self-loop + bias ----------------
__global__ void k_agg(const float* __restrict__ bias, float* __restrict__ out) {
    int n = blockIdx.x, t = threadIdx.x;
    __shared__ int   ss[64];
    __shared__ float sc[64];
    float di = g_dinv[n];
    float acc = g_xw[(size_t)n * HID + t] * (di * di) + bias[t];
    int beg = g_off[n], cnt = g_cnt[n];
    for (int base = 0; base < cnt; base += 64) {
        int nb = min(64, cnt - base);
        if (t < nb) {
            ss[t] = g_srcl[beg + base + t];
            sc[t] = g_coef[beg + base + t];
        }
        __syncthreads();
        for (int j = 0; j < nb; j++)
            acc += sc[j] * g_xw[(size_t)ss[j] * HID + t];
        __syncthreads();
    }
    out[(size_t)n * HID + t] = acc;
}

// ---------------- launch: fork/join overlap of GEMM chain vs edge chain ------
extern "C" void kernel_launch(void* const* d_in, const int* in_sizes, int n_in,
                              void* d_out, int out_size) {
    const float* U  = (const float*)d_in[0];
    const float* I  = (const float*)d_in[1];
    const int*   ei = (const int*)  d_in[2];
    const float* W1 = (const float*)d_in[3];
    const float* b1 = (const float*)d_in[4];
    const float* W2 = (const float*)d_in[5];
    const float* b2 = (const float*)d_in[6];
    const float* GW = (const float*)d_in[7];
    const float* Gb = (const float*)d_in[8];
    int E = in_sizes[2] / 2;

    float* out  = (float*)d_out;
    float* wout = out + (size_t)NN * HID;

    static cudaStream_t s2 = nullptr;
    static cudaEvent_t evFork = nullptr, evJoin = nullptr;
    if (!s2) {
        cudaStreamCreateWithFlags(&s2, cudaStreamNonBlocking);
        cudaEventCreateWithFlags(&evFork, cudaEventDisableTiming);
        cudaEventCreateWithFlags(&evJoin, cudaEventDisableTiming);
    }

    // fork: side stream runs the GEMM chain (independent of the edge chain)
    cudaEventRecord(evFork, 0);
    cudaStreamWaitEvent(s2, evFork, 0);
    k_prepW<<<HID * HID / 256, 256, 0, s2>>>(GW);
    k_gemm_hmma<<<dim3((NN + 127) / 128, HID / 128), 256, 0, s2>>>(U, I);
    cudaEventRecord(evJoin, s2);

    // main (legacy) stream: attention / denoise / CSR chain
    k_init<<<(NN + 255) / 256, 256>>>();
    k_projA<<<UBLKS + IBLKS, 256>>>(U, I, W1, b1);
    k_edge<<<((E + 3) / 4 * 32 + 255) / 256, 256>>>(ei, W2, b2, E);
    k_mask<<<(E + 255) / 256, 256>>>(ei, wout, E);
    k_dinv<<<(NN + 255) / 256, 256>>>();
    k_scan<<<1, 1024>>>();
    k_fill<<<(E + 255) / 256, 256>>>(ei, E);

    // join: aggregate needs both g_xw and the CSR
    cudaStreamWaitEvent(0, evJoin, 0);
    k_agg<<<NN, 256>>>(Gb, out);
}

// round 9
// speedup vs baseline: 2.1639x; 1.1642x over previous
#include <cuda_runtime.h>
#include <cuda_bf16.h>
#include <cstdint>

#define HID 256
#define AH  32
#define NU  10000
#define NI  30000
#define NN  40000
#define NE  500000
#define THRESH 0.8f

typedef unsigned long long ull;

// ---------------- device scratch ----------------
__device__ float g_UW1[NU * AH];
__device__ float g_IW1[NI * AH];
__device__ float g_w[NE];
__device__ float g_xw[(size_t)NN * HID];
__device__ float g_dinv[NN];
__device__ int   g_cnt[NN];
__device__ int   g_off[NN];
__device__ int   g_cur[NN];
__device__ int   g_srcl[NE];
__device__ float g_coef[NE];
__device__ ull   g_amax;
__device__ int   g_kept;
__device__ __align__(16) __nv_bfloat16 g_Bhi[HID * HID];          // W^T hi [n][k]
__device__ __align__(16) __nv_bfloat16 g_Blo[HID * HID];          // W^T lo [n][k]
__device__ __align__(16) __nv_bfloat16 g_Xhi[(size_t)NN * HID];   // X hi
__device__ __align__(16) __nv_bfloat16 g_Xlo[(size_t)NN * HID];   // X lo

// ---------------- helpers ----------------
__device__ __forceinline__ uint32_t s2u(const void* p) {
    uint32_t a;
    asm("{ .reg .u64 t; cvta.to.shared.u64 t, %1; cvt.u32.u64 %0, t; }" : "=r"(a) : "l"(p));
    return a;
}
__device__ __forceinline__ void ldsm4(uint32_t* r, uint32_t addr) {
    asm volatile("ldmatrix.sync.aligned.m8n8.x4.shared.b16 {%0,%1,%2,%3}, [%4];"
                 : "=r"(r[0]), "=r"(r[1]), "=r"(r[2]), "=r"(r[3]) : "r"(addr));
}
__device__ __forceinline__ void mma16816(float* c, const uint32_t* a, const uint32_t* b) {
    asm volatile("mma.sync.aligned.m16n8k16.row.col.f32.bf16.bf16.f32 "
                 "{%0,%1,%2,%3}, {%4,%5,%6,%7}, {%8,%9}, {%0,%1,%2,%3};"
                 : "+f"(c[0]), "+f"(c[1]), "+f"(c[2]), "+f"(c[3])
                 : "r"(a[0]), "r"(a[1]), "r"(a[2]), "r"(a[3]), "r"(b[0]), "r"(b[1]));
}
__device__ __forceinline__ ull pk2(float x, float y) {
    ull r; asm("mov.b64 %0, {%1, %2};" : "=l"(r) : "f"(x), "f"(y)); return r;
}
__device__ __forceinline__ void ffma2(ull& d, ull a, ull b) {
    asm("fma.rn.f32x2 %0, %1, %2, %0;" : "+l"(d) : "l"(a), "l"(b));
}
__device__ __forceinline__ void cpa16(uint32_t dst, const void* src) {
    asm volatile("cp.async.cg.shared.global [%0], [%1], 16;" :: "r"(dst), "l"(src) : "memory");
}
__device__ __forceinline__ void cpa_commit() { asm volatile("cp.async.commit_group;" ::: "memory"); }

// ---------------- K0: reset ----------------
__global__ void k_init() {
    int i = blockIdx.x * blockDim.x + threadIdx.x;
    if (i < NN) g_cnt[i] = 0;
    if (i == 0) { g_amax = 0ULL; g_kept = 0; }
}

// ---------------- prepW: transpose + bf16 hi/lo split of gcn_W ----------------
__global__ void k_prepW(const float* __restrict__ W) {
    int i = blockIdx.x * blockDim.x + threadIdx.x;   // 65536
    int n = i & 255, k = i >> 8;
    float v = W[k * HID + n];
    __nv_bfloat16 h = __float2bfloat16(v);
    g_Bhi[n * HID + k] = h;
    g_Blo[n * HID + k] = __float2bfloat16(v - __bfloat162float(h));
}

// ---------------- prepX: bf16 hi/lo split of concat(U,I) ----------------
__global__ void k_prepX(const float* __restrict__ U, const float* __restrict__ I) {
    size_t i = ((size_t)blockIdx.x * 256 + threadIdx.x) * 4;  // grid 10000 exact
    int m = (int)(i >> 8), k = (int)(i & 255);
    const float* x = (m < NU) ? U + (size_t)m * HID : I + (size_t)(m - NU) * HID;
    float4 v = *(const float4*)(x + k);
    __nv_bfloat16 h0 = __float2bfloat16(v.x), h1 = __float2bfloat16(v.y);
    __nv_bfloat16 h2 = __float2bfloat16(v.z), h3 = __float2bfloat16(v.w);
    __nv_bfloat16 l0 = __float2bfloat16(v.x - __bfloat162float(h0));
    __nv_bfloat16 l1 = __float2bfloat16(v.y - __bfloat162float(h1));
    __nv_bfloat16 l2 = __float2bfloat16(v.z - __bfloat162float(h2));
    __nv_bfloat16 l3 = __float2bfloat16(v.w - __bfloat162float(h3));
    __nv_bfloat162 hp0, hp1, lp0, lp1;
    hp0.x = h0; hp0.y = h1; hp1.x = h2; hp1.y = h3;
    lp0.x = l0; lp0.y = l1; lp1.x = l2; lp1.y = l3;
    *(uint2*)(g_Xhi + i) = make_uint2(*(uint32_t*)&hp0, *(uint32_t*)&hp1);
    *(uint2*)(g_Xlo + i) = make_uint2(*(uint32_t*)&lp0, *(uint32_t*)&lp1);
}

// ---------------- K1: merged node projection, f32x2 packed ----------------
#define UB2 ((NU + 127) / 128)   // 79
#define IB2 ((NI + 127) / 128)   // 235
__global__ void k_projB(const float* __restrict__ U, const float* __restrict__ I,
                        const float* __restrict__ W1, const float* __restrict__ b1) {
    __shared__ float Xs[32][130];
    __shared__ float Ws[32][32];
    const float* X; const float* Wp; const float* bv; float* P;
    int nrows, m0;
    if (blockIdx.x < UB2) {
        X = U;  Wp = W1;            bv = b1;      P = g_UW1; nrows = NU;
        m0 = blockIdx.x * 128;
    } else {
        X = I;  Wp = W1 + HID * AH; bv = nullptr; P = g_IW1; nrows = NI;
        m0 = (blockIdx.x - UB2) * 128;
    }
    int tid = threadIdx.x;
    int tr = tid >> 4, tc = tid & 15;
    ull acc[4][2] = {};
    for (int kc = 0; kc < HID; kc += 32) {
        if (kc) __syncthreads();
        for (int i = tid; i < 1024; i += 256) {
            int r = i >> 3, q = i & 7;
            int m = m0 + r; if (m >= nrows) m = nrows - 1;
            float4 v = *(const float4*)(X + (size_t)m * HID + kc + q * 4);
            Xs[q*4+0][r] = v.x; Xs[q*4+1][r] = v.y;
            Xs[q*4+2][r] = v.z; Xs[q*4+3][r] = v.w;
        }
        {
            int r = tid >> 3, q = tid & 7;
            *(float4*)&Ws[r][q * 4] = *(const float4*)(Wp + (size_t)(kc + r) * AH + q * 4);
        }
        __syncthreads();
        #pragma unroll
        for (int k = 0; k < 32; k++) {
            ull a0 = *(const ull*)&Xs[k][tr * 8 + 0];
            ull a1 = *(const ull*)&Xs[k][tr * 8 + 2];
            ull a2 = *(const ull*)&Xs[k][tr * 8 + 4];
            ull a3 = *(const ull*)&Xs[k][tr * 8 + 6];
            float2 bw = *(const float2*)&Ws[k][tc * 2];
            ull b0 = pk2(bw.x, bw.x), b1 = pk2(bw.y, bw.y);
            ffma2(acc[0][0], a0, b0); ffma2(acc[0][1], a0, b1);
            ffma2(acc[1][0], a1, b0); ffma2(acc[1][1], a1, b1);
            ffma2(acc[2][0], a2, b0); ffma2(acc[2][1], a2, b1);
            ffma2(acc[3][0], a3, b0); ffma2(acc[3][1], a3, b1);
        }
    }
    float bb0 = bv ? bv[tc * 2] : 0.f, bb1 = bv ? bv[tc * 2 + 1] : 0.f;
    #pragma unroll
    for (int i = 0; i < 4; i++) {
        float2 c0 = *(float2*)&acc[i][0];   // (row0, row1) @ col0
        float2 c1 = *(float2*)&acc[i][1];   // (row0, row1) @ col1
        int r0 = m0 + tr * 8 + 2 * i;
        if (r0 < nrows)
            *(float2*)&P[(size_t)r0 * AH + tc * 2] = make_float2(c0.x + bb0, c1.x + bb1);
        if (r0 + 1 < nrows)
            *(float2*)&P[(size_t)(r0 + 1) * AH + tc * 2] = make_float2(c0.y + bb0, c1.y + bb1);
    }
}

// ---------------- K2: edge attention (8 lanes per edge) ----------------
__global__ void k_edge(const int* __restrict__ ei, const float* __restrict__ W2,
                       const float* __restrict__ b2, int E) {
    __shared__ float sW2[AH];
    __shared__ ull   blkmax;
    __shared__ int   blkkept;
    int tid = threadIdx.x;
    if (tid < AH) sW2[tid] = W2[tid];
    if (tid == 0) { blkmax = 0ULL; blkkept = 0; }
    __syncthreads();

    int lane = tid & 31;
    int gw = (blockIdx.x * blockDim.x + tid) >> 5;
    int sub = lane >> 3, part = lane & 7;
    int e = gw * 4 + sub;
    bool valid = e < E;
    int s = 0, d = 0;
    if (valid) { s = ei[e]; d = ei[E + e]; }

    float4 a = *(const float4*)(g_UW1 + (size_t)s * AH + part * 4);
    float4 b = *(const float4*)(g_IW1 + (size_t)d * AH + part * 4);
    float h0 = a.x + b.x, h1 = a.y + b.y, h2 = a.z + b.z, h3 = a.w + b.w;
    h0 = h0 >= 0.f ? h0 : 0.2f * h0;
    h1 = h1 >= 0.f ? h1 : 0.2f * h1;
    h2 = h2 >= 0.f ? h2 : 0.2f * h2;
    h3 = h3 >= 0.f ? h3 : 0.2f * h3;
    float pz = h0 * sW2[part*4] + h1 * sW2[part*4+1] + h2 * sW2[part*4+2] + h3 * sW2[part*4+3];
    pz += __shfl_down_sync(0xFFFFFFFFu, pz, 4, 8);
    pz += __shfl_down_sync(0xFFFFFFFFu, pz, 2, 8);
    pz += __shfl_down_sync(0xFFFFFFFFu, pz, 1, 8);

    float w = -1.0f;
    if (part == 0 && valid) {
        w = 1.0f / (1.0f + expf(-(pz + b2[0])));
        g_w[e] = w;
    }
    unsigned kb = __ballot_sync(0xFFFFFFFFu, w > THRESH);
    ull p = 0ULL;
    if (part == 0 && valid)
        p = (((ull)__float_as_uint(w)) << 32) | (ull)(0xFFFFFFFFu - (unsigned)e);
    { ull q = __shfl_down_sync(0xFFFFFFFFu, p, 16); if (q > p) p = q; }
    { ull q = __shfl_down_sync(0xFFFFFFFFu, p,  8); if (q > p) p = q; }
    if (lane == 0) {
        if (kb) atomicAdd(&blkkept, __popc(kb));
        atomicMax(&blkmax, p);
    }
    __syncthreads();
    if (tid == 0) {
        if (blkkept) atomicAdd(&g_kept, blkkept);
        else         atomicMax(&g_amax, blkmax);
    }
}

__device__ __forceinline__ bool edge_kept(int e, float w) {
    if (g_kept > 0) return (w > THRESH);
    int am = (int)(0xFFFFFFFFu - (unsigned)(g_amax & 0xFFFFFFFFull));
    return (e == am);
}

// ---------------- K3: mask + denoised weights + histogram ----------------
__global__ void k_mask(const int* __restrict__ ei, float* __restrict__ wout, int E) {
    int e = blockIdx.x * blockDim.x + threadIdx.x;
    if (e >= E) return;
    float w = g_w[e];
    bool keep = edge_kept(e, w);
    wout[e] = keep ? w : 0.0f;
    if (keep) atomicAdd(&g_cnt[ei[E + e]], 1);
}

// ---------------- K4a: dinv (deg = 1 + cnt) ----------------
__global__ void k_dinv() {
    int i = blockIdx.x * blockDim.x + threadIdx.x;
    if (i < NN) g_dinv[i] = rsqrtf(1.0f + (float)g_cnt[i]);
}

// ---------------- K4b: single-block scan ----------------
#define SCHUNK 40
__global__ void k_scan() {
    __shared__ int wsum[32];
    int t = threadIdx.x;
    int lane = t & 31, wid = t >> 5;
    int base = t * SCHUNK;
    int v[SCHUNK];
    int s = 0;
    #pragma unroll
    for (int i = 0; i < SCHUNK; i++) {
        int idx = base + i;
        v[i] = (idx < NN) ? g_cnt[idx] : 0;
        s += v[i];
    }
    int incl = s;
    #pragma unroll
    for (int o = 1; o < 32; o <<= 1) {
        int u = __shfl_up_sync(0xFFFFFFFFu, incl, o);
        if (lane >= o) incl += u;
    }
    if (lane == 31) wsum[wid] = incl;
    __syncthreads();
    if (wid == 0) {
        int ws = wsum[lane];
        #pragma unroll
        for (int o = 1; o < 32; o <<= 1) {
            int u = __shfl_up_sync(0xFFFFFFFFu, ws, o);
            if (lane >= o) ws += u;
        }
        wsum[lane] = ws;
    }
    __syncthreads();
    int excl = incl - s + (wid > 0 ? wsum[wid - 1] : 0);
    #pragma unroll
    for (int i = 0; i < SCHUNK; i++) {
        int idx = base + i;
        if (idx < NN) { g_off[idx] = excl; g_cur[idx] = excl; }
        excl += v[i];
    }
}

// ---------------- K5: CSR bucket fill ----------------
__global__ void k_fill(const int* __restrict__ ei, int E) {
    int e = blockIdx.x * blockDim.x + threadIdx.x;
    if (e >= E) return;
    float w = g_w[e];
    if (!edge_kept(e, w)) return;
    int s = ei[e], d = ei[E + e];
    int p = atomicAdd(&g_cur[d], 1);
    g_srcl[p] = s;
    g_coef[p] = g_dinv[s] * g_dinv[d];
}

// ---------------- K6: HMMA bf16 3-pass GEMM, cp.async double-buffered ----------
#define ASTR 40
#define STG_A_H 0
#define STG_A_L 10240
#define STG_B_H 20480
#define STG_B_L 30720
#define STG_SZ  40960
#define GSMEM   (2 * STG_SZ)   // 81920 B

__global__ void __launch_bounds__(256, 2) k_gemm_hmma() {
    extern __shared__ char smem[];
    uint32_t sb = s2u(smem);
    int tid = threadIdx.x, warp = tid >> 5, lane = tid & 31;
    int m0 = blockIdx.x * 128, n0 = blockIdx.y * 128;
    int wm = warp >> 2, wn = warp & 3;

    int g = lane >> 3, r8 = lane & 7;
    uint32_t aoff = (uint32_t)((wm * 64 + (g & 1) * 8 + r8) * (ASTR * 2) + (g >> 1) * 16);
    uint32_t boff = (uint32_t)((wn * 32 + (g >> 1) * 8 + r8) * (ASTR * 2) + (g & 1) * 16);

    float acc[4][4][4];
    #pragma unroll
    for (int i = 0; i < 4; i++)
        #pragma unroll
        for (int j = 0; j < 4; j++)
            #pragma unroll
            for (int q = 0; q < 4; q++) acc[i][j][q] = 0.f;

    auto load_stage = [&](int kc, int stg) {
        uint32_t base = sb + (uint32_t)stg * STG_SZ;
        #pragma unroll
        for (int rep = 0; rep < 2; rep++) {
            int i = rep * 256 + tid;
            int r = i >> 2, q = i & 3;
            int m = m0 + r; if (m >= NN) m = NN - 1;
            uint32_t off = (uint32_t)(r * 80 + q * 16);
            size_t asrc = (size_t)m * HID + kc + q * 8;
            size_t bsrc = (size_t)(n0 + r) * HID + kc + q * 8;
            cpa16(base + STG_A_H + off, g_Xhi + asrc);
            cpa16(base + STG_A_L + off, g_Xlo + asrc);
            cpa16(base + STG_B_H + off, g_Bhi + bsrc);
            cpa16(base + STG_B_L + off, g_Blo + bsrc);
        }
    };

    load_stage(0, 0); cpa_commit();

    #pragma unroll 1
    for (int c = 0; c < 8; c++) {
        if (c < 7) { load_stage((c + 1) * 32, (c + 1) & 1); cpa_commit(); }
        if (c < 7) asm volatile("cp.async.wait_group 1;" ::: "memory");
        else       asm volatile("cp.async.wait_group 0;" ::: "memory");
        __syncthreads();

        uint32_t base = sb + (uint32_t)(c & 1) * STG_SZ;
        uint32_t sAh = base + STG_A_H + aoff, sAl = base + STG_A_L + aoff;
        uint32_t sBh = base + STG_B_H + boff, sBl = base + STG_B_L + boff;

        #pragma unroll
        for (int ks = 0; ks < 2; ks++) {
            uint32_t a[4][4], bh[2][4], bl[2][4];
            uint32_t kb = (uint32_t)(ks * 32);
            #pragma unroll
            for (int mf = 0; mf < 4; mf++) ldsm4(a[mf], sAh + mf * (16 * ASTR * 2) + kb);
            #pragma unroll
            for (int j = 0; j < 2; j++) ldsm4(bh[j], sBh + j * (16 * ASTR * 2) + kb);
            #pragma unroll
            for (int j = 0; j < 2; j++) ldsm4(bl[j], sBl + j * (16 * ASTR * 2) + kb);
            #pragma unroll
            for (int mf = 0; mf < 4; mf++)
                #pragma unroll
                for (int j = 0; j < 2; j++) {
                    mma16816(acc[mf][j*2+0], a[mf], &bh[j][0]);
                    mma16816(acc[mf][j*2+1], a[mf], &bh[j][2]);
                    mma16816(acc[mf][j*2+0], a[mf], &bl[j][0]);
                    mma16816(acc[mf][j*2+1], a[mf], &bl[j][2]);
                }
            #pragma unroll
            for (int mf = 0; mf < 4; mf++) ldsm4(a[mf], sAl + mf * (16 * ASTR * 2) + kb);
            #pragma unroll
            for (int mf = 0; mf < 4; mf++)
                #pragma unroll
                for (int j = 0; j < 2; j++) {
                    mma16816(acc[mf][j*2+0], a[mf], &bh[j][0]);
                    mma16816(acc[mf][j*2+1], a[mf], &bh[j][2]);
                }
        }
        __syncthreads();
    }

    int qr = lane >> 2, qc = (lane & 3) * 2;
    #pragma unroll
    for (int mf = 0; mf < 4; mf++) {
        int mrow = m0 + wm * 64 + mf * 16 + qr;
        #pragma unroll
        for (int nf = 0; nf < 4; nf++) {
            int col = n0 + wn * 32 + nf * 8 + qc;
            if (mrow < NN)
                *(float2*)&g_xw[(size_t)mrow * HID + col] = make_float2(acc[mf][nf][0], acc[mf][nf][1]);
            if (mrow + 8 < NN)
                *(float2*)&g_xw[(size_t)(mrow + 8) * HID + col] = make_float2(acc[mf][nf][2], acc[mf][nf][3]);
        }
    }
}

// ---------------- K7: per-node aggregate + self-loop + bias ----------------
__global__ void k_agg(const float* __restrict__ bias, float* __restrict__ out) {
    int n = blockIdx.x, t = threadIdx.x;
    __shared__ int   ss[64];
    __shared__ float sc[64];
    float di = g_dinv[n];
    float acc = g_xw[(size_t)n * HID + t] * (di * di) + bias[t];
    int beg = g_off[n], cnt = g_cnt[n];
    for (int base = 0; base < cnt; base += 64) {
        int nb = min(64, cnt - base);
        if (t < nb) {
            ss[t] = g_srcl[beg + base + t];
            sc[t] = g_coef[beg + base + t];
        }
        __syncthreads();
        for (int j = 0; j < nb; j++)
            acc += sc[j] * g_xw[(size_t)ss[j] * HID + t];
        __syncthreads();
    }
    out[(size_t)n * HID + t] = acc;
}

// ---------------- launch: fork/join overlap ----------------
extern "C" void kernel_launch(void* const* d_in, const int* in_sizes, int n_in,
                              void* d_out, int out_size) {
    const float* U  = (const float*)d_in[0];
    const float* I  = (const float*)d_in[1];
    const int*   ei = (const int*)  d_in[2];
    const float* W1 = (const float*)d_in[3];
    const float* b1 = (const float*)d_in[4];
    const float* W2 = (const float*)d_in[5];
    const float* b2 = (const float*)d_in[6];
    const float* GW = (const float*)d_in[7];
    const float* Gb = (const float*)d_in[8];
    int E = in_sizes[2] / 2;

    float* out  = (float*)d_out;
    float* wout = out + (size_t)NN * HID;

    static cudaStream_t s2 = nullptr;
    static cudaEvent_t evFork = nullptr, evJoin = nullptr;
    if (!s2) {
        cudaStreamCreateWithFlags(&s2, cudaStreamNonBlocking);
        cudaEventCreateWithFlags(&evFork, cudaEventDisableTiming);
        cudaEventCreateWithFlags(&evJoin, cudaEventDisableTiming);
        cudaFuncSetAttribute(k_gemm_hmma, cudaFuncAttributeMaxDynamicSharedMemorySize, GSMEM);
    }

    // fork: side stream runs the GEMM chain
    cudaEventRecord(evFork, 0);
    cudaStreamWaitEvent(s2, evFork, 0);
    k_prepW<<<HID * HID / 256, 256, 0, s2>>>(GW);
    k_prepX<<<(int)(((size_t)NN * HID / 4) / 256), 256, 0, s2>>>(U, I);
    k_gemm_hmma<<<dim3((NN + 127) / 128, HID / 128), 256, GSMEM, s2>>>();
    cudaEventRecord(evJoin, s2);

    // main stream: attention / denoise / CSR chain
    k_init<<<(NN + 255) / 256, 256>>>();
    k_projB<<<UB2 + IB2, 256>>>(U, I, W1, b1);
    k_edge<<<((E + 3) / 4 * 32 + 255) / 256, 256>>>(ei, W2, b2, E);
    k_mask<<<(E + 255) / 256, 256>>>(ei, wout, E);
    k_dinv<<<(NN + 255) / 256, 256>>>();
    k_scan<<<1, 1024>>>();
    k_fill<<<(E + 255) / 256, 256>>>(ei, E);

    // join: aggregate needs both g_xw and the CSR
    cudaStreamWaitEvent(0, evJoin, 0);
    k_agg<<<NN, 256>>>(Gb, out);
}